// round 7
// baseline (speedup 1.0000x reference)
#include <cuda_runtime.h>
#include <cuda_bf16.h>
#include <math.h>
#include <stdint.h>

#define Bn 128
#define Tn 512
#define Dn 256
#define Vn 4096
#define Sn 512

// ---------------------------------------------------------------------------
// Device scratch (no cudaMalloc allowed)
// ---------------------------------------------------------------------------
__device__ float          g_pre[Bn * Tn * Dn];          // fp32 pre-activations
__device__ __nv_bfloat16  g_hH[Bn * Tn * Dn];           // hidden hi
__device__ __nv_bfloat16  g_hL[Bn * Tn * Dn];           // hidden lo
__device__ __nv_bfloat16  g_embH[Vn * Dn], g_embL[Vn * Dn];
__device__ __nv_bfloat16  g_w0H[Dn * Dn],  g_w0L[Dn * Dn];
__device__ __nv_bfloat16  g_w1H[Dn * Dn],  g_w1L[Dn * Dn];
__device__ __nv_bfloat16  g_whH[Sn * Dn],  g_whL[Sn * Dn];

// ---------------------------------------------------------------------------
// mma.sync / ldmatrix helpers (sm_80-era PTX: legal under compute_103)
// ---------------------------------------------------------------------------
__device__ __forceinline__ uint32_t smem_u32(const void* p) {
    uint32_t a;
    asm("{ .reg .u64 t; cvta.to.shared.u64 t, %1; cvt.u32.u64 %0, t; }"
        : "=r"(a) : "l"(p));
    return a;
}
__device__ __forceinline__ void ldsm4(uint32_t r[4], uint32_t addr) {
    asm volatile("ldmatrix.sync.aligned.m8n8.x4.shared.b16 {%0,%1,%2,%3}, [%4];"
                 : "=r"(r[0]), "=r"(r[1]), "=r"(r[2]), "=r"(r[3]) : "r"(addr));
}
__device__ __forceinline__ void mma_bf16(float d[4], const uint32_t a[4],
                                         const uint32_t b[2]) {
    asm volatile(
        "mma.sync.aligned.m16n8k16.row.col.f32.bf16.bf16.f32 "
        "{%0,%1,%2,%3}, {%4,%5,%6,%7}, {%8,%9}, {%0,%1,%2,%3};"
        : "+f"(d[0]), "+f"(d[1]), "+f"(d[2]), "+f"(d[3])
        : "r"(a[0]), "r"(a[1]), "r"(a[2]), "r"(a[3]), "r"(b[0]), "r"(b[1]));
}

// ---------------------------------------------------------------------------
// Tensor-core GEMM:  C[M][N] = (AH+AL)[M][256] * (BH+BL)[N][256]^T (+b1[n]+b2[n])
// bf16 hi/lo split (3 products), fp32 register accumulate. (round-4, passing)
// ---------------------------------------------------------------------------
#define A_PITCH 528
#define B_PITCH 80
#define SM_AH   0
#define SM_AL   (128 * A_PITCH)
#define SM_B    (2 * 128 * A_PITCH)
#define B_SEG   (128 * B_PITCH)
#define GEMM_SMEM (SM_B + 4 * B_SEG)

__global__ __launch_bounds__(256, 1) void gemm_mma(
    const __nv_bfloat16* __restrict__ AH, const __nv_bfloat16* __restrict__ AL,
    const int* __restrict__ ids,
    const __nv_bfloat16* __restrict__ BH, const __nv_bfloat16* __restrict__ BL,
    const float* __restrict__ b1, const float* __restrict__ b2,
    float* __restrict__ C, int N)
{
    extern __shared__ char gsm[];
    const uint32_t sb = smem_u32(gsm);

    const int tid = threadIdx.x;
    const int wid = tid >> 5, lane = tid & 31;
    const int warp_m = wid >> 2;
    const int warp_n = wid & 3;
    const int m0 = blockIdx.x * 128;

#pragma unroll 4
    for (int i = tid; i < 4096; i += 256) {
        int row = i >> 5, seg = i & 31;
        int src = ids ? __ldg(ids + m0 + row) : (m0 + row);
        const uint4* gh = (const uint4*)(AH + (size_t)src * 256 + seg * 8);
        const uint4* gl = (const uint4*)(AL + (size_t)src * 256 + seg * 8);
        *(uint4*)(gsm + SM_AH + row * A_PITCH + seg * 16) = *gh;
        *(uint4*)(gsm + SM_AL + row * A_PITCH + seg * 16) = *gl;
    }

    const int aRow = warp_m * 64 + (lane & 15);
    const uint32_t aOff = (uint32_t)aRow * A_PITCH + ((lane >> 4) * 8) * 2;
    const uint32_t aBaseH = sb + SM_AH + aOff;
    const uint32_t aBaseL = sb + SM_AL + aOff;
    const int bN = warp_n * 32 + (lane & 7) + ((lane >> 4) << 3);
    const uint32_t bOff = (uint32_t)bN * B_PITCH + ((lane >> 3) & 1) * 16;
    const uint32_t bBase = sb + SM_B + bOff;

    const int lrow = tid >> 1;
    const int lseg = (tid & 1) * 2;

    const int nTiles = N >> 7;
#pragma unroll 1
    for (int nt = 0; nt < nTiles; nt++) {
        const int n0 = nt << 7;

        float acc[4][4][4];
#pragma unroll
        for (int i = 0; i < 4; i++)
#pragma unroll
            for (int j = 0; j < 4; j++)
#pragma unroll
                for (int r = 0; r < 4; r++) acc[i][j][r] = 0.f;

        __syncthreads();

        {
            const __nv_bfloat16* gh = BH + (size_t)(n0 + lrow) * 256 + lseg * 8;
            const __nv_bfloat16* gl = BL + (size_t)(n0 + lrow) * 256 + lseg * 8;
            uint4 h0 = *(const uint4*)gh, h1 = *(const uint4*)(gh + 8);
            uint4 l0 = *(const uint4*)gl, l1 = *(const uint4*)(gl + 8);
            char* dh = gsm + SM_B + 0 * B_SEG + lrow * B_PITCH + lseg * 16;
            char* dl = gsm + SM_B + 1 * B_SEG + lrow * B_PITCH + lseg * 16;
            *(uint4*)dh = h0; *(uint4*)(dh + 16) = h1;
            *(uint4*)dl = l0; *(uint4*)(dl + 16) = l1;
        }
        __syncthreads();

#pragma unroll 1
        for (int kc = 0; kc < 8; kc++) {
            const int s = kc & 1;

            uint4 h0, h1, l0, l1;
            if (kc < 7) {
                const __nv_bfloat16* gh =
                    BH + (size_t)(n0 + lrow) * 256 + (kc + 1) * 32 + lseg * 8;
                const __nv_bfloat16* gl =
                    BL + (size_t)(n0 + lrow) * 256 + (kc + 1) * 32 + lseg * 8;
                h0 = *(const uint4*)gh; h1 = *(const uint4*)(gh + 8);
                l0 = *(const uint4*)gl; l1 = *(const uint4*)(gl + 8);
            }

#pragma unroll
            for (int kk = 0; kk < 2; kk++) {
                const uint32_t aK = (uint32_t)(kc * 2 + kk) * 32;
                uint32_t aH[4][4], aL[4][4];
#pragma unroll
                for (int i = 0; i < 4; i++) {
                    ldsm4(aH[i], aBaseH + i * (16 * A_PITCH) + aK);
                    ldsm4(aL[i], aBaseL + i * (16 * A_PITCH) + aK);
                }
                uint32_t bH[2][4], bL[2][4];
#pragma unroll
                for (int p = 0; p < 2; p++) {
                    uint32_t o = (uint32_t)p * (16 * B_PITCH) + (uint32_t)kk * 32;
                    ldsm4(bH[p], bBase + (s * 2 + 0) * B_SEG + o);
                    ldsm4(bL[p], bBase + (s * 2 + 1) * B_SEG + o);
                }
#pragma unroll
                for (int i = 0; i < 4; i++)
#pragma unroll
                    for (int j = 0; j < 4; j++)
                        mma_bf16(acc[i][j], aH[i], &bH[j >> 1][(j & 1) * 2]);
#pragma unroll
                for (int i = 0; i < 4; i++)
#pragma unroll
                    for (int j = 0; j < 4; j++)
                        mma_bf16(acc[i][j], aH[i], &bL[j >> 1][(j & 1) * 2]);
#pragma unroll
                for (int i = 0; i < 4; i++)
#pragma unroll
                    for (int j = 0; j < 4; j++)
                        mma_bf16(acc[i][j], aL[i], &bH[j >> 1][(j & 1) * 2]);
            }

            if (kc < 7) {
                __syncthreads();
                char* dh = gsm + SM_B + ((s ^ 1) * 2 + 0) * B_SEG +
                           lrow * B_PITCH + lseg * 16;
                char* dl = gsm + SM_B + ((s ^ 1) * 2 + 1) * B_SEG +
                           lrow * B_PITCH + lseg * 16;
                *(uint4*)dh = h0; *(uint4*)(dh + 16) = h1;
                *(uint4*)dl = l0; *(uint4*)(dl + 16) = l1;
                __syncthreads();
            }
        }

        const int rBase = m0 + warp_m * 64 + (lane >> 2);
        const int cBase = n0 + warp_n * 32 + (lane & 3) * 2;
#pragma unroll
        for (int j = 0; j < 4; j++) {
            const int col = cBase + j * 8;
            float bb0 = 0.f, bb1 = 0.f;
            if (b1) {
                bb0 = b1[col] + b2[col];
                bb1 = b1[col + 1] + b2[col + 1];
            }
#pragma unroll
            for (int i = 0; i < 4; i++) {
                const int row = rBase + i * 16;
                float2 v0 = make_float2(acc[i][j][0] + bb0, acc[i][j][1] + bb1);
                float2 v1 = make_float2(acc[i][j][2] + bb0, acc[i][j][3] + bb1);
                *(float2*)(C + (size_t)row * N + col) = v0;
                *(float2*)(C + (size_t)(row + 8) * N + col) = v1;
            }
        }
    }
}

// ---------------------------------------------------------------------------
// fp32 -> bf16 hi/lo split converter
// ---------------------------------------------------------------------------
__global__ void conv_split(const float* __restrict__ src,
                           __nv_bfloat16* __restrict__ hi,
                           __nv_bfloat16* __restrict__ lo, int n)
{
    int i = blockIdx.x * 256 + threadIdx.x;
    if (i < n) {
        float v = src[i];
        __nv_bfloat16 h = __float2bfloat16(v);
        hi[i] = h;
        lo[i] = __float2bfloat16(v - __bfloat162float(h));
    }
}

// ---------------------------------------------------------------------------
// Recurrence v5: K-split, 512 threads, W 100% register-resident.
//   h_t = tanh(pre_t + W_hh @ h_{t-1})
// Thread (j, half) owns W[j][half*128 .. half*128+127] in 32 float4 REGISTERS
// (zero W shared-memory traffic). Each computes a half-K partial; partials
// combined through a 2KB smem buffer; low 256 threads do tanh + in-place h
// update + bf16 hi/lo emit. 16 warps (4/SMSP) hide LDS/barrier latency.
// Per-SM/step: FFMA-pipe floor 1024 cyc; LDS wavefronts ~550 (was ~1024).
// ---------------------------------------------------------------------------
__global__ void __launch_bounds__(512, 1) rnn_recur(
    const float* __restrict__ pre,        // [B][T][D]
    const float* __restrict__ Whh,        // [D][D]
    __nv_bfloat16* __restrict__ houtH,    // [B][T][D]
    __nv_bfloat16* __restrict__ houtL)
{
    __shared__ float hA[256];
    __shared__ float part[512];           // part[2*j + half]

    const int tid  = threadIdx.x;
    const int j    = tid & 255;
    const int half = tid >> 8;
    const int b    = blockIdx.x;

    // W registers: row j, cols [half*128, half*128+128)
    float4 wr[32];
    {
        const float4* wrow =
            (const float4*)(Whh + (size_t)j * 256 + half * 128);
#pragma unroll
        for (int q = 0; q < 32; q++) wr[q] = wrow[q];
    }

    if (half == 0) hA[j] = 0.f;
    __syncthreads();

    const float*   prow = pre   + ((size_t)b * Tn) * Dn;
    __nv_bfloat16* ohr  = houtH + ((size_t)b * Tn) * Dn;
    __nv_bfloat16* olr  = houtL + ((size_t)b * Tn) * Dn;

    const float4* hb = ((const float4*)hA) + half * 32;

    float pcur = (half == 0) ? prow[j] : 0.f;

#pragma unroll 1
    for (int step = 0; step < Tn; step++) {
        // half-K dot product (W in registers, h broadcast from smem)
        float a0 = 0.f, a1 = 0.f, a2 = 0.f, a3 = 0.f;
#pragma unroll
        for (int q = 0; q < 32; q++) {
            float4 h = hb[q];
            float4 w = wr[q];
            a0 = fmaf(w.x, h.x, a0);
            a1 = fmaf(w.y, h.y, a1);
            a2 = fmaf(w.z, h.z, a2);
            a3 = fmaf(w.w, h.w, a3);
        }
        float ps = (a0 + a1) + (a2 + a3);

        // prefetch next pre (combine threads only)
        float pnext = 0.f;
        if (half == 0 && step + 1 < Tn) pnext = prow[Dn + j];

        part[2 * j + half] = ps;
        __syncthreads();                 // all hA reads + partials done

        if (half == 0) {
            float2 pp = *(const float2*)&part[2 * j];
            float v = tanhf(pcur + pp.x + pp.y);
            hA[j] = v;                   // in-place: safe, readers are past
            __nv_bfloat16 vh = __float2bfloat16(v);
            ohr[j] = vh;
            olr[j] = __float2bfloat16(v - __bfloat162float(vh));
            pcur = pnext;
        }
        __syncthreads();                 // h_t visible to all

        prow += Dn; ohr += Dn; olr += Dn;
    }
}

// ---------------------------------------------------------------------------
extern "C" void kernel_launch(void* const* d_in, const int* in_sizes, int n_in,
                              void* d_out, int out_size)
{
    (void)in_sizes; (void)n_in; (void)out_size;

    const int*   ids   = (const int*)  d_in[0];
    const float* emb   = (const float*)d_in[1];
    const float* Wih0  = (const float*)d_in[2];
    const float* Whh0  = (const float*)d_in[3];
    const float* bih0  = (const float*)d_in[4];
    const float* bhh0  = (const float*)d_in[5];
    const float* Wih1  = (const float*)d_in[6];
    const float* Whh1  = (const float*)d_in[7];
    const float* bih1  = (const float*)d_in[8];
    const float* bhh1  = (const float*)d_in[9];
    const float* Whead = (const float*)d_in[10];
    float* out = (float*)d_out;

    float *pre;           cudaGetSymbolAddress((void**)&pre,  g_pre);
    __nv_bfloat16 *hH;    cudaGetSymbolAddress((void**)&hH,   g_hH);
    __nv_bfloat16 *hL;    cudaGetSymbolAddress((void**)&hL,   g_hL);
    __nv_bfloat16 *embH;  cudaGetSymbolAddress((void**)&embH, g_embH);
    __nv_bfloat16 *embL;  cudaGetSymbolAddress((void**)&embL, g_embL);
    __nv_bfloat16 *w0H;   cudaGetSymbolAddress((void**)&w0H,  g_w0H);
    __nv_bfloat16 *w0L;   cudaGetSymbolAddress((void**)&w0L,  g_w0L);
    __nv_bfloat16 *w1H;   cudaGetSymbolAddress((void**)&w1H,  g_w1H);
    __nv_bfloat16 *w1L;   cudaGetSymbolAddress((void**)&w1L,  g_w1L);
    __nv_bfloat16 *whH;   cudaGetSymbolAddress((void**)&whH,  g_whH);
    __nv_bfloat16 *whL;   cudaGetSymbolAddress((void**)&whL,  g_whL);

    cudaFuncSetAttribute(gemm_mma, cudaFuncAttributeMaxDynamicSharedMemorySize,
                         GEMM_SMEM);

    // Weight / embedding bf16 hi-lo splits
    conv_split<<<(Vn * Dn + 255) / 256, 256>>>(emb,   embH, embL, Vn * Dn);
    conv_split<<<(Dn * Dn + 255) / 256, 256>>>(Wih0,  w0H,  w0L,  Dn * Dn);
    conv_split<<<(Dn * Dn + 255) / 256, 256>>>(Wih1,  w1H,  w1L,  Dn * Dn);
    conv_split<<<(Sn * Dn + 255) / 256, 256>>>(Whead, whH,  whL,  Sn * Dn);

    const int M = Bn * Tn;   // 65536

    // pre0 = emb[ids] @ W_ih0^T + (b_ih0 + b_hh0)
    gemm_mma<<<M / 128, 256, GEMM_SMEM>>>(embH, embL, ids, w0H, w0L,
                                          bih0, bhh0, pre, Dn);
    // h1 recurrence (emits bf16 hi/lo)
    rnn_recur<<<Bn, 512>>>(pre, Whh0, hH, hL);
    // pre1 = h1 @ W_ih1^T + (b_ih1 + b_hh1)
    gemm_mma<<<M / 128, 256, GEMM_SMEM>>>(hH, hL, nullptr, w1H, w1L,
                                          bih1, bhh1, pre, Dn);
    // h2 recurrence
    rnn_recur<<<Bn, 512>>>(pre, Whh1, hH, hL);
    // logits = h2 @ W_head^T
    gemm_mma<<<M / 128, 256, GEMM_SMEM>>>(hH, hL, nullptr, whH, whL,
                                          nullptr, nullptr, out, Sn);
}

// round 8
// speedup vs baseline: 2.0579x; 2.0579x over previous
#include <cuda_runtime.h>
#include <cuda_bf16.h>
#include <math.h>
#include <stdint.h>

#define Bn 128
#define Tn 512
#define Dn 256
#define Vn 4096
#define Sn 512

// ---------------------------------------------------------------------------
// Device scratch (no cudaMalloc allowed)
// ---------------------------------------------------------------------------
__device__ float          g_pre[Bn * Tn * Dn];          // fp32 pre-activations
__device__ __nv_bfloat16  g_hH[Bn * Tn * Dn];           // hidden hi
__device__ __nv_bfloat16  g_hL[Bn * Tn * Dn];           // hidden lo
__device__ __nv_bfloat16  g_embH[Vn * Dn], g_embL[Vn * Dn];
__device__ __nv_bfloat16  g_w0H[Dn * Dn],  g_w0L[Dn * Dn];
__device__ __nv_bfloat16  g_w1H[Dn * Dn],  g_w1L[Dn * Dn];
__device__ __nv_bfloat16  g_whH[Sn * Dn],  g_whL[Sn * Dn];

// ---------------------------------------------------------------------------
// mma.sync / ldmatrix / cp.async helpers (sm_80-era PTX: legal under compute_103)
// ---------------------------------------------------------------------------
__device__ __forceinline__ uint32_t smem_u32(const void* p) {
    uint32_t a;
    asm("{ .reg .u64 t; cvta.to.shared.u64 t, %1; cvt.u32.u64 %0, t; }"
        : "=r"(a) : "l"(p));
    return a;
}
__device__ __forceinline__ void ldsm4(uint32_t r[4], uint32_t addr) {
    asm volatile("ldmatrix.sync.aligned.m8n8.x4.shared.b16 {%0,%1,%2,%3}, [%4];"
                 : "=r"(r[0]), "=r"(r[1]), "=r"(r[2]), "=r"(r[3]) : "r"(addr));
}
__device__ __forceinline__ void mma_bf16(float d[4], const uint32_t a[4],
                                         const uint32_t b[2]) {
    asm volatile(
        "mma.sync.aligned.m16n8k16.row.col.f32.bf16.bf16.f32 "
        "{%0,%1,%2,%3}, {%4,%5,%6,%7}, {%8,%9}, {%0,%1,%2,%3};"
        : "+f"(d[0]), "+f"(d[1]), "+f"(d[2]), "+f"(d[3])
        : "r"(a[0]), "r"(a[1]), "r"(a[2]), "r"(a[3]), "r"(b[0]), "r"(b[1]));
}
__device__ __forceinline__ void cpa16(uint32_t saddr, const void* g) {
    asm volatile("cp.async.cg.shared.global [%0], [%1], 16;"
                 :: "r"(saddr), "l"(g) : "memory");
}
#define CPA_COMMIT() asm volatile("cp.async.commit_group;" ::: "memory")
#define CPA_WAIT2()  asm volatile("cp.async.wait_group 2;" ::: "memory")

// ---------------------------------------------------------------------------
// Tensor-core GEMM:  C[M][N] = (AH+AL)[M][256] * (BH+BL)[N][256]^T (+b1[n]+b2[n])
// bf16 hi/lo split (3 products), fp32 register accumulate.
// v2: cp.async 4-stage pipeline for B chunks; A tile loaded via cp.async once.
// One __syncthreads per K-chunk (was 2 + sync loads). 8 warps = 2(m) x 4(n).
// ---------------------------------------------------------------------------
#define A_PITCH 528
#define B_PITCH 80
#define SM_AH   0
#define SM_AL   (128 * A_PITCH)
#define SM_B    (2 * 128 * A_PITCH)            // 135168
#define B_SEG   (128 * B_PITCH)                // 10240 (one half, one stage)
#define NSTAGE  4
#define GEMM_SMEM (SM_B + NSTAGE * 2 * B_SEG)  // 217088 B

__global__ __launch_bounds__(256, 1) void gemm_mma(
    const __nv_bfloat16* __restrict__ AH, const __nv_bfloat16* __restrict__ AL,
    const int* __restrict__ ids,
    const __nv_bfloat16* __restrict__ BH, const __nv_bfloat16* __restrict__ BL,
    const float* __restrict__ b1, const float* __restrict__ b2,
    float* __restrict__ C, int N)
{
    extern __shared__ char gsm[];
    const uint32_t sb = smem_u32(gsm);

    const int tid = threadIdx.x;
    const int wid = tid >> 5, lane = tid & 31;
    const int warp_m = wid >> 2;
    const int warp_n = wid & 3;
    const int m0 = blockIdx.x * 128;

    // ---- A tile (128 x 256, hi+lo) via cp.async; one commit group ----
#pragma unroll 4
    for (int i = tid; i < 4096; i += 256) {
        int row = i >> 5, seg = i & 31;
        int src = ids ? __ldg(ids + m0 + row) : (m0 + row);
        cpa16(sb + SM_AH + row * A_PITCH + seg * 16,
              AH + (size_t)src * 256 + seg * 8);
        cpa16(sb + SM_AL + row * A_PITCH + seg * 16,
              AL + (size_t)src * 256 + seg * 8);
    }
    CPA_COMMIT();

    // ---- Per-lane ldmatrix addresses ----
    const int aRow = warp_m * 64 + (lane & 15);
    const uint32_t aOff = (uint32_t)aRow * A_PITCH + ((lane >> 4) * 8) * 2;
    const uint32_t aBaseH = sb + SM_AH + aOff;
    const uint32_t aBaseL = sb + SM_AL + aOff;
    const int bN = warp_n * 32 + (lane & 7) + ((lane >> 4) << 3);
    const uint32_t bOff = (uint32_t)bN * B_PITCH + ((lane >> 3) & 1) * 16;

    // ---- B chunk loader mapping (per thread: 2 x 16B per half) ----
    const int lrow = tid >> 1;               // 0..127
    const int lseg = (tid & 1) * 2;          // 16B unit 0 or 2 (of 4)
    const uint32_t bstW = sb + SM_B + lrow * B_PITCH + lseg * 16;

    const int nTiles = N >> 7;
#pragma unroll 1
    for (int nt = 0; nt < nTiles; nt++) {
        const int n0 = nt << 7;

        float acc[4][4][4];
#pragma unroll
        for (int i = 0; i < 4; i++)
#pragma unroll
            for (int j = 0; j < 4; j++)
#pragma unroll
                for (int r = 0; r < 4; r++) acc[i][j][r] = 0.f;

        // prologue: issue stages 0..2 (one commit group each)
#pragma unroll
        for (int pc = 0; pc < 3; pc++) {
            const __nv_bfloat16* gh =
                BH + (size_t)(n0 + lrow) * 256 + pc * 32 + lseg * 8;
            const __nv_bfloat16* gl =
                BL + (size_t)(n0 + lrow) * 256 + pc * 32 + lseg * 8;
            uint32_t d = bstW + pc * (2 * B_SEG);
            cpa16(d, gh);             cpa16(d + 16, gh + 8);
            cpa16(d + B_SEG, gl);     cpa16(d + B_SEG + 16, gl + 8);
            CPA_COMMIT();
        }

#pragma unroll 1
        for (int kc = 0; kc < 8; kc++) {
            CPA_WAIT2();            // stage kc (and A, nt=0) complete
            __syncthreads();        // visible CTA-wide

            const uint32_t hiB = sb + SM_B + (uint32_t)(kc & 3) * (2 * B_SEG) + bOff;
            const uint32_t loB = hiB + B_SEG;

            // issue stage kc+3 (slot (kc+3)&3 == (kc-1)&3, reads done last iter)
            if (kc < 5) {
                const __nv_bfloat16* gh =
                    BH + (size_t)(n0 + lrow) * 256 + (kc + 3) * 32 + lseg * 8;
                const __nv_bfloat16* gl =
                    BL + (size_t)(n0 + lrow) * 256 + (kc + 3) * 32 + lseg * 8;
                uint32_t d = bstW + (uint32_t)((kc + 3) & 3) * (2 * B_SEG);
                cpa16(d, gh);             cpa16(d + 16, gh + 8);
                cpa16(d + B_SEG, gl);     cpa16(d + B_SEG + 16, gl + 8);
            }
            CPA_COMMIT();           // empty group when kc >= 5 (keeps count uniform)

            // MMA over this chunk (two k16 steps)
#pragma unroll
            for (int kk = 0; kk < 2; kk++) {
                const uint32_t aK = (uint32_t)(kc * 2 + kk) * 32;
                uint32_t aH[4][4], aL[4][4];
#pragma unroll
                for (int i = 0; i < 4; i++) {
                    ldsm4(aH[i], aBaseH + i * (16 * A_PITCH) + aK);
                    ldsm4(aL[i], aBaseL + i * (16 * A_PITCH) + aK);
                }
                uint32_t bH[2][4], bL[2][4];
#pragma unroll
                for (int p = 0; p < 2; p++) {
                    uint32_t o = (uint32_t)p * (16 * B_PITCH) + (uint32_t)kk * 32;
                    ldsm4(bH[p], hiB + o);
                    ldsm4(bL[p], loB + o);
                }
#pragma unroll
                for (int i = 0; i < 4; i++)
#pragma unroll
                    for (int j = 0; j < 4; j++)
                        mma_bf16(acc[i][j], aH[i], &bH[j >> 1][(j & 1) * 2]);
#pragma unroll
                for (int i = 0; i < 4; i++)
#pragma unroll
                    for (int j = 0; j < 4; j++)
                        mma_bf16(acc[i][j], aH[i], &bL[j >> 1][(j & 1) * 2]);
#pragma unroll
                for (int i = 0; i < 4; i++)
#pragma unroll
                    for (int j = 0; j < 4; j++)
                        mma_bf16(acc[i][j], aL[i], &bH[j >> 1][(j & 1) * 2]);
            }
        }

        // ---- Epilogue: add bias, store fp32 C ----
        const int rBase = m0 + warp_m * 64 + (lane >> 2);
        const int cBase = n0 + warp_n * 32 + (lane & 3) * 2;
#pragma unroll
        for (int j = 0; j < 4; j++) {
            const int col = cBase + j * 8;
            float bb0 = 0.f, bb1 = 0.f;
            if (b1) {
                bb0 = b1[col] + b2[col];
                bb1 = b1[col + 1] + b2[col + 1];
            }
#pragma unroll
            for (int i = 0; i < 4; i++) {
                const int row = rBase + i * 16;
                float2 v0 = make_float2(acc[i][j][0] + bb0, acc[i][j][1] + bb1);
                float2 v1 = make_float2(acc[i][j][2] + bb0, acc[i][j][3] + bb1);
                *(float2*)(C + (size_t)row * N + col) = v0;
                *(float2*)(C + (size_t)(row + 8) * N + col) = v1;
            }
        }
    }
}

// ---------------------------------------------------------------------------
// fp32 -> bf16 hi/lo split converter
// ---------------------------------------------------------------------------
__global__ void conv_split(const float* __restrict__ src,
                           __nv_bfloat16* __restrict__ hi,
                           __nv_bfloat16* __restrict__ lo, int n)
{
    int i = blockIdx.x * 256 + threadIdx.x;
    if (i < n) {
        float v = src[i];
        __nv_bfloat16 h = __float2bfloat16(v);
        hi[i] = h;
        lo[i] = __float2bfloat16(v - __bfloat162float(h));
    }
}

// ---------------------------------------------------------------------------
// Recurrence (round-4 proven version, byte-identical): one CTA per batch row.
//   h_t = tanh(pre_t + W_hh @ h_{t-1})
// Thread j owns output row j: W[j][0:192] in 48 float4 registers,
// W[:][192:256] via smem pitch-17-float4; h double-buffered, 1 barrier/step.
// Emits h as bf16 hi/lo for the GEMM A-operand.
// ---------------------------------------------------------------------------
#define WREG 48
#define WSMQ 16
#define WPITCH4 17

__device__ __forceinline__ float rnn_dot(
    const float4* __restrict__ wr, const float4* __restrict__ wsr,
    const float4* __restrict__ hb)
{
    float a0 = 0.f, a1 = 0.f, a2 = 0.f, a3 = 0.f;
#pragma unroll
    for (int q = 0; q < WREG; q++) {
        float4 h = hb[q];
        float4 w = wr[q];
        a0 = fmaf(w.x, h.x, a0);
        a1 = fmaf(w.y, h.y, a1);
        a2 = fmaf(w.z, h.z, a2);
        a3 = fmaf(w.w, h.w, a3);
    }
#pragma unroll
    for (int q = 0; q < WSMQ; q++) {
        float4 h = hb[WREG + q];
        float4 w = wsr[q];
        a0 = fmaf(w.x, h.x, a0);
        a1 = fmaf(w.y, h.y, a1);
        a2 = fmaf(w.z, h.z, a2);
        a3 = fmaf(w.w, h.w, a3);
    }
    return (a0 + a1) + (a2 + a3);
}

extern __shared__ float smem_r[];

__global__ void __launch_bounds__(256, 1) rnn_recur(
    const float* __restrict__ pre,        // [B][T][D]
    const float* __restrict__ Whh,        // [D][D]
    __nv_bfloat16* __restrict__ houtH,    // [B][T][D]
    __nv_bfloat16* __restrict__ houtL)
{
    float4* Wsm = (float4*)smem_r;
    float*  hA  = smem_r + 256 * WPITCH4 * 4;
    float*  hB  = hA + 256;

    int b = blockIdx.x;
    int j = threadIdx.x;

    float4 wr[WREG];
    {
        const float4* wrow = (const float4*)(Whh + (size_t)j * 256);
#pragma unroll
        for (int q = 0; q < WREG; q++) wr[q] = wrow[q];
    }
    for (int i = j; i < 256 * WSMQ; i += 256) {
        int r = i >> 4, c = i & 15;
        Wsm[r * WPITCH4 + c] =
            ((const float4*)(Whh + (size_t)r * 256 + WREG * 4))[c];
    }

    hA[j] = 0.f;
    __syncthreads();

    const float*   prow = pre   + ((size_t)b * Tn) * Dn;
    __nv_bfloat16* ohr  = houtH + ((size_t)b * Tn) * Dn;
    __nv_bfloat16* olr  = houtL + ((size_t)b * Tn) * Dn;
    const float4*  wsr  = Wsm + j * WPITCH4;

    float pcur = prow[j];

#pragma unroll 1
    for (int step = 0; step < Tn; step += 2) {
        {
            float pnext = prow[Dn + j];
            float s = rnn_dot(wr, wsr, (const float4*)hA);
            float v = tanhf(pcur + s);
            hB[j] = v;
            __nv_bfloat16 vh = __float2bfloat16(v);
            ohr[j] = vh;
            olr[j] = __float2bfloat16(v - __bfloat162float(vh));
            __syncthreads();
            pcur = pnext; prow += Dn; ohr += Dn; olr += Dn;
        }
        {
            float pnext = (step + 2 < Tn) ? prow[Dn + j] : 0.f;
            float s = rnn_dot(wr, wsr, (const float4*)hB);
            float v = tanhf(pcur + s);
            hA[j] = v;
            __nv_bfloat16 vh = __float2bfloat16(v);
            ohr[j] = vh;
            olr[j] = __float2bfloat16(v - __bfloat162float(vh));
            __syncthreads();
            pcur = pnext; prow += Dn; ohr += Dn; olr += Dn;
        }
    }
}

// ---------------------------------------------------------------------------
extern "C" void kernel_launch(void* const* d_in, const int* in_sizes, int n_in,
                              void* d_out, int out_size)
{
    (void)in_sizes; (void)n_in; (void)out_size;

    const int*   ids   = (const int*)  d_in[0];
    const float* emb   = (const float*)d_in[1];
    const float* Wih0  = (const float*)d_in[2];
    const float* Whh0  = (const float*)d_in[3];
    const float* bih0  = (const float*)d_in[4];
    const float* bhh0  = (const float*)d_in[5];
    const float* Wih1  = (const float*)d_in[6];
    const float* Whh1  = (const float*)d_in[7];
    const float* bih1  = (const float*)d_in[8];
    const float* bhh1  = (const float*)d_in[9];
    const float* Whead = (const float*)d_in[10];
    float* out = (float*)d_out;

    float *pre;           cudaGetSymbolAddress((void**)&pre,  g_pre);
    __nv_bfloat16 *hH;    cudaGetSymbolAddress((void**)&hH,   g_hH);
    __nv_bfloat16 *hL;    cudaGetSymbolAddress((void**)&hL,   g_hL);
    __nv_bfloat16 *embH;  cudaGetSymbolAddress((void**)&embH, g_embH);
    __nv_bfloat16 *embL;  cudaGetSymbolAddress((void**)&embL, g_embL);
    __nv_bfloat16 *w0H;   cudaGetSymbolAddress((void**)&w0H,  g_w0H);
    __nv_bfloat16 *w0L;   cudaGetSymbolAddress((void**)&w0L,  g_w0L);
    __nv_bfloat16 *w1H;   cudaGetSymbolAddress((void**)&w1H,  g_w1H);
    __nv_bfloat16 *w1L;   cudaGetSymbolAddress((void**)&w1L,  g_w1L);
    __nv_bfloat16 *whH;   cudaGetSymbolAddress((void**)&whH,  g_whH);
    __nv_bfloat16 *whL;   cudaGetSymbolAddress((void**)&whL,  g_whL);

    const int recur_smem = (256 * WPITCH4 * 4 + 512) * 4;   // 71680 B
    cudaFuncSetAttribute(rnn_recur, cudaFuncAttributeMaxDynamicSharedMemorySize,
                         recur_smem);
    cudaFuncSetAttribute(gemm_mma, cudaFuncAttributeMaxDynamicSharedMemorySize,
                         GEMM_SMEM);

    // Weight / embedding bf16 hi-lo splits
    conv_split<<<(Vn * Dn + 255) / 256, 256>>>(emb,   embH, embL, Vn * Dn);
    conv_split<<<(Dn * Dn + 255) / 256, 256>>>(Wih0,  w0H,  w0L,  Dn * Dn);
    conv_split<<<(Dn * Dn + 255) / 256, 256>>>(Wih1,  w1H,  w1L,  Dn * Dn);
    conv_split<<<(Sn * Dn + 255) / 256, 256>>>(Whead, whH,  whL,  Sn * Dn);

    const int M = Bn * Tn;   // 65536

    // pre0 = emb[ids] @ W_ih0^T + (b_ih0 + b_hh0)
    gemm_mma<<<M / 128, 256, GEMM_SMEM>>>(embH, embL, ids, w0H, w0L,
                                          bih0, bhh0, pre, Dn);
    // h1 recurrence (emits bf16 hi/lo)
    rnn_recur<<<Bn, 256, recur_smem>>>(pre, Whh0, hH, hL);
    // pre1 = h1 @ W_ih1^T + (b_ih1 + b_hh1)
    gemm_mma<<<M / 128, 256, GEMM_SMEM>>>(hH, hL, nullptr, w1H, w1L,
                                          bih1, bhh1, pre, Dn);
    // h2 recurrence
    rnn_recur<<<Bn, 256, recur_smem>>>(pre, Whh1, hH, hL);
    // logits = h2 @ W_head^T
    gemm_mma<<<M / 128, 256, GEMM_SMEM>>>(hH, hL, nullptr, whH, whL,
                                          nullptr, nullptr, out, Sn);
}